// round 11
// baseline (speedup 1.0000x reference)
#include <cuda_runtime.h>
#include <cuda_bf16.h>
#include <math.h>
#include <stdint.h>

#define D_MODEL 1024
#define NHEADS  16
#define HDIM    64
#define HALF    32
#define BB      2
#define SS      2048
#define MTOK    (BB*SS)          // 4096 tokens
#define NROWS   (BB*NHEADS*SS)   // 65536 head-rows
#define KW      (D_MODEL/2)      // 512 packed words per row

// Scratch (static __device__ arrays — no allocations allowed)
__device__ float g_qkv[MTOK * 3 * D_MODEL];     // GEMM1 output (fp32)
__device__ float g_ropet[SS * HALF * 2];        // cos/sin table
// packed bf16 hi/lo pairs (2 bf16 per uint32)
__device__ __align__(16) uint32_t g_xh [MTOK * KW],      g_xl [MTOK * KW];
__device__ __align__(16) uint32_t g_w1h[3*D_MODEL * KW], g_w1l[3*D_MODEL * KW];
__device__ __align__(16) uint32_t g_w2h[D_MODEL * KW],   g_w2l[D_MODEL * KW];
__device__ __align__(16) uint32_t g_ah [MTOK * KW],      g_al [MTOK * KW];   // flash out
__device__ __align__(16) uint32_t g_qh[NROWS*32], g_ql[NROWS*32];
__device__ __align__(16) uint32_t g_kh[NROWS*32], g_kl[NROWS*32];
__device__ __align__(16) uint32_t g_vh[NROWS*32], g_vl[NROWS*32];

// ===========================================================================
// helpers
// ===========================================================================
__device__ __forceinline__ uint32_t smem_u32(const void* p) {
    uint32_t a;
    asm("{ .reg .u64 t; cvta.to.shared.u64 t, %1; cvt.u32.u64 %0, t; }"
        : "=r"(a) : "l"(p));
    return a;
}
__device__ __forceinline__ void ldmx4(uint32_t* r, uint32_t addr) {
    asm volatile("ldmatrix.sync.aligned.m8n8.x4.shared.b16 {%0,%1,%2,%3}, [%4];"
                 : "=r"(r[0]), "=r"(r[1]), "=r"(r[2]), "=r"(r[3]) : "r"(addr));
}
__device__ __forceinline__ void ldmx4t(uint32_t* r, uint32_t addr) {
    asm volatile("ldmatrix.sync.aligned.m8n8.x4.trans.shared.b16 {%0,%1,%2,%3}, [%4];"
                 : "=r"(r[0]), "=r"(r[1]), "=r"(r[2]), "=r"(r[3]) : "r"(addr));
}
__device__ __forceinline__ void mma16816(float* c, const uint32_t* a,
                                         uint32_t b0, uint32_t b1) {
    asm volatile(
        "mma.sync.aligned.m16n8k16.row.col.f32.bf16.bf16.f32 "
        "{%0,%1,%2,%3}, {%4,%5,%6,%7}, {%8,%9}, {%0,%1,%2,%3};"
        : "+f"(c[0]), "+f"(c[1]), "+f"(c[2]), "+f"(c[3])
        : "r"(a[0]), "r"(a[1]), "r"(a[2]), "r"(a[3]), "r"(b0), "r"(b1));
}
__device__ __forceinline__ uint32_t pack_hi(float x, float y,
                                            float& rx, float& ry) {
    __nv_bfloat16 hx = __float2bfloat16(x);
    __nv_bfloat16 hy = __float2bfloat16(y);
    rx = x - __bfloat162float(hx);
    ry = y - __bfloat162float(hy);
    return ((uint32_t)__bfloat16_as_ushort(hy) << 16) |
           (uint32_t)__bfloat16_as_ushort(hx);
}
__device__ __forceinline__ uint32_t pack_bf(float x, float y) {
    return ((uint32_t)__bfloat16_as_ushort(__float2bfloat16(y)) << 16) |
           (uint32_t)__bfloat16_as_ushort(__float2bfloat16(x));
}
__device__ __forceinline__ void cpa16(uint32_t saddr, const void* g) {
    asm volatile("cp.async.cg.shared.global [%0], [%1], 16;"
                 :: "r"(saddr), "l"(g));
}
__device__ __forceinline__ void cpa_commit() {
    asm volatile("cp.async.commit_group;" ::: "memory");
}
template <int N> __device__ __forceinline__ void cpa_wait() {
    asm volatile("cp.async.wait_group %0;" :: "n"(N) : "memory");
}

// ===========================================================================
// split_pack: float pairs -> packed bf16 hi/lo
// ===========================================================================
__global__ void split_pack(const float2* __restrict__ in,
                           uint32_t* __restrict__ hi,
                           uint32_t* __restrict__ lo, int n)
{
    int i = blockIdx.x * 256 + threadIdx.x;
    if (i < n) {
        float2 v = in[i];
        float l0, l1;
        hi[i] = pack_hi(v.x, v.y, l0, l1);
        lo[i] = pack_bf(l0, l1);
    }
}

// ===========================================================================
// GEMM v3: BK=64, register fragment double-buffering, 1 CTA/SM (255 regs).
// C[M,N] = A@W^T + bias.  Pitch 144B (conflict-free ldmatrix, gcd(9,8)=1).
// 2 stages x 72KB smem.
// ===========================================================================
#define GPIT  144            // pitch bytes per row (32 data words + 4 pad)
#define GARB  18432          // bytes per array (128*144)
#define GSTB  73728          // stage bytes (4 arrays)
#define GAHB  0
#define GALB  18432
#define GBHB  36864
#define GBLB  55296
#define GSMEM (2*GSTB)       // 147456

struct GFrag { uint32_t bh[2][4], bl[2][4], ah[4][4], al[4][4]; };

__global__ void __launch_bounds__(256)
gemm_pk(const uint32_t* __restrict__ Apk_h, const uint32_t* __restrict__ Apk_l,
        const uint32_t* __restrict__ Wpk_h, const uint32_t* __restrict__ Wpk_l,
        const float* __restrict__ bias, float* __restrict__ C,
        int M, int N, int Kw)
{
    extern __shared__ char sm[];
    const uint32_t smb = smem_u32(sm);
    const int tid  = threadIdx.x;
    const int wid  = tid >> 5;
    const int lane = tid & 31;
    const int row0 = blockIdx.y * 128;
    const int col0 = blockIdx.x * 128;
    const int wm   = (wid >> 2) * 64;
    const int wn   = (wid & 3) * 32;

    const int nkb = Kw >> 5;            // 32 packed words (K=64 fp32) per block

    auto prefetch = [&](int kb) {
        const uint32_t sb = smb + (kb & 1) * GSTB;
        const int kw0 = kb << 5;
#pragma unroll
        for (int i = 0; i < 16; i++) {
            int slot = tid + i * 256;           // 0..4095
            int arr  = slot >> 10;              // 0..3
            int rem  = slot & 1023;
            int r    = rem >> 3;                // 0..127
            int ch   = (rem & 7) << 2;          // word chunk 0..28
            uint32_t sa = sb + (uint32_t)arr * GARB + r * GPIT + ch * 4;
            const uint32_t* gp;
            if (arr == 0)      gp = Apk_h + (size_t)(row0 + r) * Kw + kw0 + ch;
            else if (arr == 1) gp = Apk_l + (size_t)(row0 + r) * Kw + kw0 + ch;
            else if (arr == 2) gp = Wpk_h + (size_t)(col0 + r) * Kw + kw0 + ch;
            else               gp = Wpk_l + (size_t)(col0 + r) * Kw + kw0 + ch;
            cpa16(sa, gp);
        }
        cpa_commit();
    };

    float acc[4][4][4];
#pragma unroll
    for (int mt = 0; mt < 4; mt++)
#pragma unroll
        for (int nt = 0; nt < 4; nt++)
#pragma unroll
            for (int e = 0; e < 4; e++) acc[mt][nt][e] = 0.f;

    const uint32_t bln = (lane & 7) + ((lane >> 4) << 3);
    const uint32_t blk = ((lane >> 3) & 1) << 3;
    const uint32_t arow = lane & 15;
    const uint32_t acol = (lane >> 4) << 3;

    auto load_frag = [&](uint32_t sb, int k16, GFrag& f) {
#pragma unroll
        for (int pr = 0; pr < 2; pr++) {
            uint32_t off = (wn + pr * 16 + bln) * GPIT + (k16 + blk) * 2;
            ldmx4(f.bh[pr], sb + GBHB + off);
            ldmx4(f.bl[pr], sb + GBLB + off);
        }
#pragma unroll
        for (int mt = 0; mt < 4; mt++) {
            uint32_t off = (wm + mt * 16 + arow) * GPIT + (k16 + acol) * 2;
            ldmx4(f.ah[mt], sb + GAHB + off);
            ldmx4(f.al[mt], sb + GALB + off);
        }
    };
    auto do_mma = [&](const GFrag& f) {
#pragma unroll
        for (int mt = 0; mt < 4; mt++)
#pragma unroll
            for (int nt = 0; nt < 4; nt++) {
                uint32_t b0h = f.bh[nt >> 1][(nt & 1) * 2];
                uint32_t b1h = f.bh[nt >> 1][(nt & 1) * 2 + 1];
                uint32_t b0l = f.bl[nt >> 1][(nt & 1) * 2];
                uint32_t b1l = f.bl[nt >> 1][(nt & 1) * 2 + 1];
                mma16816(acc[mt][nt], f.ah[mt], b0h, b1h);
                mma16816(acc[mt][nt], f.ah[mt], b0l, b1l);
                mma16816(acc[mt][nt], f.al[mt], b0h, b1h);
            }
    };

    prefetch(0);

    GFrag fr[2];
    for (int kb = 0; kb < nkb; kb++) {
        cpa_wait<0>();
        __syncthreads();
        if (kb + 1 < nkb) prefetch(kb + 1);

        const uint32_t sb = smb + (kb & 1) * GSTB;
        load_frag(sb, 0, fr[0]);
#pragma unroll
        for (int step = 0; step < 4; step++) {
            if (step < 3) load_frag(sb, (step + 1) * 16, fr[(step + 1) & 1]);
            do_mma(fr[step & 1]);
        }
    }

#pragma unroll
    for (int mt = 0; mt < 4; mt++) {
#pragma unroll
        for (int nt = 0; nt < 4; nt++) {
            int row = row0 + wm + mt * 16 + (lane >> 2);
            int col = col0 + wn + nt * 8 + (lane & 3) * 2;
            float2 bz = *(const float2*)&bias[col];
            *(float2*)(C + (size_t)row * N + col) =
                make_float2(acc[mt][nt][0] + bz.x, acc[mt][nt][1] + bz.y);
            *(float2*)(C + (size_t)(row + 8) * N + col) =
                make_float2(acc[mt][nt][2] + bz.x, acc[mt][nt][3] + bz.y);
        }
    }
}

// ---------------------------------------------------------------------------
// RoPE table + apply/split/pack (unchanged)
// ---------------------------------------------------------------------------
__global__ void rope_table_kernel()
{
    int idx = blockIdx.x * 256 + threadIdx.x;
    int s  = idx >> 5;
    int dp = idx & 31;
    double inv = pow(10000.0, -((double)dp) / (double)HALF);
    double snd, csd;
    sincos((double)s * inv, &snd, &csd);
    g_ropet[idx * 2 + 0] = (float)csd;
    g_ropet[idx * 2 + 1] = (float)snd;
}

__global__ void rope_split_kernel()
{
    int idx = blockIdx.x * 256 + threadIdx.x;
    int j = idx & 31;
    int h = (idx >> 5) & 15;
    int s = (idx >> 9) & (SS - 1);
    int b = idx >> 20;
    const float* base = g_qkv + (size_t)(b * SS + s) * (3 * D_MODEL) + h * HDIM;
    int d0 = 2 * j, d1 = d0 + 1;
    int dp0 = d0 & 31, dp1 = d1 & 31;
    float cs0 = g_ropet[(s * 32 + dp0) * 2], sn0 = g_ropet[(s * 32 + dp0) * 2 + 1];
    float cs1 = g_ropet[(s * 32 + dp1) * 2], sn1 = g_ropet[(s * 32 + dp1) * 2 + 1];
    float qv0, qv1, kv0, kv1;
    if (d0 < 32) {
        qv0 = base[d0] * cs0 - base[d0 + 32] * sn0;
        qv1 = base[d1] * cs1 - base[d1 + 32] * sn1;
        kv0 = base[D_MODEL + d0] * cs0 - base[D_MODEL + d0 + 32] * sn0;
        kv1 = base[D_MODEL + d1] * cs1 - base[D_MODEL + d1 + 32] * sn1;
    } else {
        qv0 = base[dp0] * sn0 + base[d0] * cs0;
        qv1 = base[dp1] * sn1 + base[d1] * cs1;
        kv0 = base[D_MODEL + dp0] * sn0 + base[D_MODEL + d0] * cs0;
        kv1 = base[D_MODEL + dp1] * sn1 + base[D_MODEL + d1] * cs1;
    }
    qv0 *= 0.125f; qv1 *= 0.125f;
    float vv0 = base[2 * D_MODEL + d0], vv1 = base[2 * D_MODEL + d1];

    size_t o = ((size_t)(b * NHEADS + h) * SS + s) * 32 + j;
    float l0, l1;
    g_qh[o] = pack_hi(qv0, qv1, l0, l1); g_ql[o] = pack_bf(l0, l1);
    g_kh[o] = pack_hi(kv0, kv1, l0, l1); g_kl[o] = pack_bf(l0, l1);
    g_vh[o] = pack_hi(vv0, vv1, l0, l1); g_vl[o] = pack_bf(l0, l1);
}

// ===========================================================================
// Flash attention (unchanged from round 10): single-barrier pipeline + LJF.
// ===========================================================================
#define FQHB  0
#define FQLB  18432
#define FSB0  36864
#define FSTB  36864
#define FKHB  0
#define FKLB  9216
#define FVHB  18432
#define FVLB  27648
#define FSMEM 110592

__global__ void __launch_bounds__(256, 2)
flash_mma_kernel()
{
    extern __shared__ char fsm[];
    const uint32_t smb = smem_u32(fsm);
    uint32_t* smw = (uint32_t*)fsm;
    const int tid  = threadIdx.x;
    const int wid  = tid >> 5;
    const int lane = tid & 31;
    const int bh   = blockIdx.y;
    const int qb   = gridDim.x - 1 - blockIdx.x;    // heavy CTAs launch first
    const int q0   = qb * 128;
    const int wm   = wid * 16;
    const size_t rowbase = (size_t)bh * SS;

    const int ntiles = 2 * qb + 2;

    auto prefetch = [&](int kt) {
        const uint32_t sb = smb + FSB0 + (kt & 1) * FSTB;
        const int k0 = kt * 64;
#pragma unroll
        for (int i = 0; i < 8; i++) {
            int slot = tid + i * 256;
            int arr  = slot >> 9;
            int rem  = slot & 511;
            int r    = rem >> 3;
            int ch   = (rem & 7) << 2;
            uint32_t sa = sb + (uint32_t)arr * 9216 + r * 144 + ch * 4;
            size_t gi = (rowbase + k0 + r) * 32 + ch;
            const uint32_t* gp;
            if (arr == 0)      gp = g_kh + gi;
            else if (arr == 1) gp = g_kl + gi;
            else if (arr == 2) gp = g_vh + gi;
            else               gp = g_vl + gi;
            cpa16(sa, gp);
        }
        cpa_commit();
    };

    prefetch(0);

    // ---- Q fill (plain uint4 copies) ----
#pragma unroll
    for (int i = 0; i < 4; i++) {
        int slot = tid + i * 256;
        int r = slot >> 3, c = (slot & 7) * 4;
        size_t gi = (rowbase + q0 + r) * 32 + c;
        *(uint4*)&smw[(FQHB >> 2) + r * 36 + c] = *(const uint4*)&g_qh[gi];
        *(uint4*)&smw[(FQLB >> 2) + r * 36 + c] = *(const uint4*)&g_ql[gi];
    }
    __syncthreads();

    // ---- hoist Q a-frags ----
    uint32_t qh[4][4], ql[4][4];
    {
        const uint32_t arow = lane & 15;
        const uint32_t acol = (lane >> 4) << 3;
#pragma unroll
        for (int ks = 0; ks < 4; ks++) {
            uint32_t off = (wm + arow) * 144 + (ks * 16 + acol) * 2;
            ldmx4(qh[ks], smb + FQHB + off);
            ldmx4(ql[ks], smb + FQLB + off);
        }
    }

    float o[8][4];
#pragma unroll
    for (int nt = 0; nt < 8; nt++)
#pragma unroll
        for (int e = 0; e < 4; e++) o[nt][e] = 0.f;
    float mrun[2] = {-INFINITY, -INFINITY};
    float lrun[2] = {0.f, 0.f};

    const uint32_t bln = (lane & 7) + ((lane >> 4) << 3);
    const uint32_t blk = ((lane >> 3) & 1) << 3;
    const uint32_t vrow = (lane & 7) + (((lane >> 3) & 1) << 3);
    const uint32_t vcol = (lane >> 4) << 3;

    for (int kt = 0; kt < ntiles; kt++) {
        const int k0 = kt * 64;
        cpa_wait<0>();
        __syncthreads();
        if (kt + 1 < ntiles) prefetch(kt + 1);

        const uint32_t sb = smb + FSB0 + (kt & 1) * FSTB;

        if (k0 <= q0 + wm + 15) {
            // ---- S = Q K^T ----
            float sc[8][4];
#pragma unroll
            for (int nt = 0; nt < 8; nt++)
#pragma unroll
                for (int e = 0; e < 4; e++) sc[nt][e] = 0.f;
#pragma unroll
            for (int ks = 0; ks < 4; ks++) {
#pragma unroll
                for (int pr = 0; pr < 4; pr++) {
                    uint32_t kh[4], kl[4];
                    uint32_t off = (pr * 16 + bln) * 144 + (ks * 16 + blk) * 2;
                    ldmx4(kh, sb + FKHB + off);
                    ldmx4(kl, sb + FKLB + off);
                    mma16816(sc[2*pr],   qh[ks], kh[0], kh[1]);
                    mma16816(sc[2*pr],   qh[ks], kl[0], kl[1]);
                    mma16816(sc[2*pr],   ql[ks], kh[0], kh[1]);
                    mma16816(sc[2*pr+1], qh[ks], kh[2], kh[3]);
                    mma16816(sc[2*pr+1], qh[ks], kl[2], kl[3]);
                    mma16816(sc[2*pr+1], ql[ks], kh[2], kh[3]);
                }
            }

            // ---- causal mask on straddling tiles ----
            if (k0 + 63 > q0 + wm) {
                int row0g = q0 + wm + (lane >> 2);
#pragma unroll
                for (int nt = 0; nt < 8; nt++) {
                    int colg = k0 + nt * 8 + (lane & 3) * 2;
                    if (colg     > row0g)     sc[nt][0] = -INFINITY;
                    if (colg + 1 > row0g)     sc[nt][1] = -INFINITY;
                    if (colg     > row0g + 8) sc[nt][2] = -INFINITY;
                    if (colg + 1 > row0g + 8) sc[nt][3] = -INFINITY;
                }
            }

            // ---- online softmax ----
#pragma unroll
            for (int hrow = 0; hrow < 2; hrow++) {
                const int e0 = hrow * 2;
                float mx = -INFINITY;
#pragma unroll
                for (int nt = 0; nt < 8; nt++)
                    mx = fmaxf(mx, fmaxf(sc[nt][e0], sc[nt][e0 + 1]));
                mx = fmaxf(mx, __shfl_xor_sync(0xffffffffu, mx, 1));
                mx = fmaxf(mx, __shfl_xor_sync(0xffffffffu, mx, 2));
                float mn    = fmaxf(mrun[hrow], mx);
                float alpha = __expf(mrun[hrow] - mn);
                float ls = 0.f;
#pragma unroll
                for (int nt = 0; nt < 8; nt++) {
                    float p0 = __expf(sc[nt][e0]     - mn);
                    float p1 = __expf(sc[nt][e0 + 1] - mn);
                    sc[nt][e0] = p0; sc[nt][e0 + 1] = p1;
                    ls += p0 + p1;
                }
                ls += __shfl_xor_sync(0xffffffffu, ls, 1);
                ls += __shfl_xor_sync(0xffffffffu, ls, 2);
                lrun[hrow] = lrun[hrow] * alpha + ls;
                mrun[hrow] = mn;
#pragma unroll
                for (int nt = 0; nt < 8; nt++) {
                    o[nt][e0] *= alpha; o[nt][e0 + 1] *= alpha;
                }
            }

            // ---- O += P V ----
#pragma unroll
            for (int ks = 0; ks < 4; ks++) {
                uint32_t pa[4], pl[4];
                {
                    float l0, l1, l2, l3;
                    pa[0] = pack_hi(sc[2*ks][0],   sc[2*ks][1],   l0, l1);
                    pa[1] = pack_hi(sc[2*ks][2],   sc[2*ks][3],   l2, l3);
                    pl[0] = pack_bf(l0, l1);
                    pl[1] = pack_bf(l2, l3);
                    pa[2] = pack_hi(sc[2*ks+1][0], sc[2*ks+1][1], l0, l1);
                    pa[3] = pack_hi(sc[2*ks+1][2], sc[2*ks+1][3], l2, l3);
                    pl[2] = pack_bf(l0, l1);
                    pl[3] = pack_bf(l2, l3);
                }
#pragma unroll
                for (int dp = 0; dp < 4; dp++) {
                    uint32_t vh[4], vl[4];
                    uint32_t off = (ks * 16 + vrow) * 144 + (dp * 16 + vcol) * 2;
                    ldmx4t(vh, sb + FVHB + off);
                    ldmx4t(vl, sb + FVLB + off);
                    mma16816(o[2*dp],   pa, vh[0], vh[1]);
                    mma16816(o[2*dp],   pa, vl[0], vl[1]);
                    mma16816(o[2*dp],   pl, vh[0], vh[1]);
                    mma16816(o[2*dp+1], pa, vh[2], vh[3]);
                    mma16816(o[2*dp+1], pa, vl[2], vl[3]);
                    mma16816(o[2*dp+1], pl, vh[2], vh[3]);
                }
            }
        }
    }

    // ---- epilogue: normalize + pack hi/lo directly ----
    const int b = bh >> 4, h = bh & 15;
    const float inv0 = 1.f / lrun[0];
    const float inv1 = 1.f / lrun[1];
    int row0g = q0 + wm + (lane >> 2);
#pragma unroll
    for (int nt = 0; nt < 8; nt++) {
        int cw = h * 32 + nt * 4 + (lane & 3);
        size_t o0 = (size_t)(b * SS + row0g) * KW + cw;
        size_t o1 = (size_t)(b * SS + row0g + 8) * KW + cw;
        float l0, l1;
        g_ah[o0] = pack_hi(o[nt][0] * inv0, o[nt][1] * inv0, l0, l1);
        g_al[o0] = pack_bf(l0, l1);
        g_ah[o1] = pack_hi(o[nt][2] * inv1, o[nt][3] * inv1, l0, l1);
        g_al[o1] = pack_bf(l0, l1);
    }
}

// ---------------------------------------------------------------------------
extern "C" void kernel_launch(void* const* d_in, const int* in_sizes, int n_in,
                              void* d_out, int out_size)
{
    const float* x     = 0;
    const float* qkv_w = 0;
    const float* qkv_b = 0;
    const float* out_w = 0;
    const float* out_b = 0;
    for (int i = 0; i < n_in; i++) {
        switch (in_sizes[i]) {
            case MTOK * D_MODEL:            x     = (const float*)d_in[i]; break;
            case 3 * D_MODEL * D_MODEL:     qkv_w = (const float*)d_in[i]; break;
            case 3 * D_MODEL:               qkv_b = (const float*)d_in[i]; break;
            case D_MODEL * D_MODEL:         out_w = (const float*)d_in[i]; break;
            case D_MODEL:                   out_b = (const float*)d_in[i]; break;
            default: break;
        }
    }
    float* out = (float*)d_out;

    float* qkv_p;
    uint32_t *xh_p, *xl_p, *w1h_p, *w1l_p, *w2h_p, *w2l_p, *ah_p, *al_p;
    cudaGetSymbolAddress((void**)&qkv_p, g_qkv);
    cudaGetSymbolAddress((void**)&xh_p,  g_xh);  cudaGetSymbolAddress((void**)&xl_p,  g_xl);
    cudaGetSymbolAddress((void**)&w1h_p, g_w1h); cudaGetSymbolAddress((void**)&w1l_p, g_w1l);
    cudaGetSymbolAddress((void**)&w2h_p, g_w2h); cudaGetSymbolAddress((void**)&w2l_p, g_w2l);
    cudaGetSymbolAddress((void**)&ah_p,  g_ah);  cudaGetSymbolAddress((void**)&al_p,  g_al);

    cudaFuncSetAttribute(gemm_pk,
                         cudaFuncAttributeMaxDynamicSharedMemorySize, GSMEM);
    cudaFuncSetAttribute(flash_mma_kernel,
                         cudaFuncAttributeMaxDynamicSharedMemorySize, FSMEM);

    // 0) pre-split inputs to packed bf16 hi/lo
    split_pack<<<MTOK * KW / 256, 256>>>((const float2*)x, xh_p, xl_p, MTOK * KW);
    split_pack<<<3 * D_MODEL * KW / 256, 256>>>((const float2*)qkv_w, w1h_p, w1l_p,
                                                3 * D_MODEL * KW);
    split_pack<<<D_MODEL * KW / 256, 256>>>((const float2*)out_w, w2h_p, w2l_p,
                                            D_MODEL * KW);

    // 1) QKV projection
    gemm_pk<<<dim3((3 * D_MODEL) / 128, MTOK / 128), 256, GSMEM>>>(
        xh_p, xl_p, w1h_p, w1l_p, qkv_b, qkv_p, MTOK, 3 * D_MODEL, KW);

    // 2) RoPE table + apply/split/pack
    rope_table_kernel<<<SS * HALF / 256, 256>>>();
    rope_split_kernel<<<MTOK * NHEADS * 32 / 256, 256>>>();

    // 3) causal flash attention
    flash_mma_kernel<<<dim3(SS / 128, BB * NHEADS), 256, FSMEM>>>();

    // 4) output projection
    gemm_pk<<<dim3(D_MODEL / 128, MTOK / 128), 256, GSMEM>>>(
        ah_p, al_p, w2h_p, w2l_p, out_b, out, MTOK, D_MODEL, KW);
}

// round 13
// speedup vs baseline: 1.0058x; 1.0058x over previous
#include <cuda_runtime.h>
#include <cuda_bf16.h>
#include <math.h>
#include <stdint.h>

#define D_MODEL 1024
#define NHEADS  16
#define HDIM    64
#define HALF    32
#define BB      2
#define SS      2048
#define MTOK    (BB*SS)          // 4096 tokens
#define NROWS   (BB*NHEADS*SS)   // 65536 head-rows
#define KW      (D_MODEL/2)      // 512 packed words per row

// Scratch (static __device__ arrays — no allocations allowed)
__device__ float g_qkv[MTOK * 3 * D_MODEL];     // GEMM1 output (fp32)
__device__ float g_ropet[SS * HALF * 2];        // cos/sin table
// packed bf16 hi/lo pairs (2 bf16 per uint32)
__device__ __align__(16) uint32_t g_xh [MTOK * KW],      g_xl [MTOK * KW];
__device__ __align__(16) uint32_t g_w1h[3*D_MODEL * KW], g_w1l[3*D_MODEL * KW];
__device__ __align__(16) uint32_t g_w2h[D_MODEL * KW],   g_w2l[D_MODEL * KW];
__device__ __align__(16) uint32_t g_ah [MTOK * KW],      g_al [MTOK * KW];   // flash out
__device__ __align__(16) uint32_t g_qh[NROWS*32], g_ql[NROWS*32];
__device__ __align__(16) uint32_t g_kh[NROWS*32], g_kl[NROWS*32];
__device__ __align__(16) uint32_t g_vh[NROWS*32], g_vl[NROWS*32];

// ===========================================================================
// helpers
// ===========================================================================
__device__ __forceinline__ uint32_t smem_u32(const void* p) {
    uint32_t a;
    asm("{ .reg .u64 t; cvta.to.shared.u64 t, %1; cvt.u32.u64 %0, t; }"
        : "=r"(a) : "l"(p));
    return a;
}
__device__ __forceinline__ void ldmx4(uint32_t* r, uint32_t addr) {
    asm volatile("ldmatrix.sync.aligned.m8n8.x4.shared.b16 {%0,%1,%2,%3}, [%4];"
                 : "=r"(r[0]), "=r"(r[1]), "=r"(r[2]), "=r"(r[3]) : "r"(addr));
}
__device__ __forceinline__ void ldmx4t(uint32_t* r, uint32_t addr) {
    asm volatile("ldmatrix.sync.aligned.m8n8.x4.trans.shared.b16 {%0,%1,%2,%3}, [%4];"
                 : "=r"(r[0]), "=r"(r[1]), "=r"(r[2]), "=r"(r[3]) : "r"(addr));
}
__device__ __forceinline__ void mma16816(float* c, const uint32_t* a,
                                         uint32_t b0, uint32_t b1) {
    asm volatile(
        "mma.sync.aligned.m16n8k16.row.col.f32.bf16.bf16.f32 "
        "{%0,%1,%2,%3}, {%4,%5,%6,%7}, {%8,%9}, {%0,%1,%2,%3};"
        : "+f"(c[0]), "+f"(c[1]), "+f"(c[2]), "+f"(c[3])
        : "r"(a[0]), "r"(a[1]), "r"(a[2]), "r"(a[3]), "r"(b0), "r"(b1));
}
__device__ __forceinline__ uint32_t pack_hi(float x, float y,
                                            float& rx, float& ry) {
    __nv_bfloat16 hx = __float2bfloat16(x);
    __nv_bfloat16 hy = __float2bfloat16(y);
    rx = x - __bfloat162float(hx);
    ry = y - __bfloat162float(hy);
    return ((uint32_t)__bfloat16_as_ushort(hy) << 16) |
           (uint32_t)__bfloat16_as_ushort(hx);
}
__device__ __forceinline__ uint32_t pack_bf(float x, float y) {
    return ((uint32_t)__bfloat16_as_ushort(__float2bfloat16(y)) << 16) |
           (uint32_t)__bfloat16_as_ushort(__float2bfloat16(x));
}
__device__ __forceinline__ void cpa16(uint32_t saddr, const void* g) {
    asm volatile("cp.async.cg.shared.global [%0], [%1], 16;"
                 :: "r"(saddr), "l"(g));
}
__device__ __forceinline__ void cpa_commit() {
    asm volatile("cp.async.commit_group;" ::: "memory");
}
template <int N> __device__ __forceinline__ void cpa_wait() {
    asm volatile("cp.async.wait_group %0;" :: "n"(N) : "memory");
}

// ===========================================================================
// split_pack: float pairs -> packed bf16 hi/lo
// ===========================================================================
__global__ void split_pack(const float2* __restrict__ in,
                           uint32_t* __restrict__ hi,
                           uint32_t* __restrict__ lo, int n)
{
    int i = blockIdx.x * 256 + threadIdx.x;
    if (i < n) {
        float2 v = in[i];
        float l0, l1;
        hi[i] = pack_hi(v.x, v.y, l0, l1);
        lo[i] = pack_bf(l0, l1);
    }
}

// ===========================================================================
// GEMM v4: 128x128 CTA, 4 warps (2x2), WARP TILE 64x64 -> 85 B smem per HMMA.
// BK=32 (16 words), pitch 80B (gcd(5,8)=1: conflict-free ldmatrix).
// 2 stages x 40KB smem -> 2 CTAs/SM.  Single barrier per k-block.
// ===========================================================================
#define GPIT  80             // pitch bytes per row (16 data words + 4 pad)
#define GARB  10240          // bytes per array (128*80)
#define GSTB  40960          // stage bytes (4 arrays)
#define GAHB  0
#define GALB  10240
#define GBHB  20480
#define GBLB  30720
#define GSMEM (2*GSTB)       // 81920

__global__ void __launch_bounds__(128)
gemm_pk(const uint32_t* __restrict__ Apk_h, const uint32_t* __restrict__ Apk_l,
        const uint32_t* __restrict__ Wpk_h, const uint32_t* __restrict__ Wpk_l,
        const float* __restrict__ bias, float* __restrict__ C,
        int M, int N, int Kw)
{
    extern __shared__ char sm[];
    const uint32_t smb = smem_u32(sm);
    const int tid  = threadIdx.x;
    const int wid  = tid >> 5;
    const int lane = tid & 31;
    const int row0 = blockIdx.y * 128;
    const int col0 = blockIdx.x * 128;
    const int wm   = (wid >> 1) * 64;    // warp row offset
    const int wn   = (wid & 1) * 64;     // warp col offset

    const int nkb = Kw >> 4;             // 16 packed words (K=32 fp32) per block

    auto prefetch = [&](int kb) {
        const uint32_t sb = smb + (kb & 1) * GSTB;
        const int kw0 = kb << 4;
#pragma unroll
        for (int i = 0; i < 16; i++) {
            int slot = tid + i * 128;           // 0..2047
            int arr  = slot >> 9;               // 0..3
            int rem  = slot & 511;
            int r    = rem >> 2;                // 0..127
            int ch   = (rem & 3) << 2;          // word chunk 0,4,8,12
            uint32_t sa = sb + (uint32_t)arr * GARB + r * GPIT + ch * 4;
            const uint32_t* gp;
            if (arr == 0)      gp = Apk_h + (size_t)(row0 + r) * Kw + kw0 + ch;
            else if (arr == 1) gp = Apk_l + (size_t)(row0 + r) * Kw + kw0 + ch;
            else if (arr == 2) gp = Wpk_h + (size_t)(col0 + r) * Kw + kw0 + ch;
            else               gp = Wpk_l + (size_t)(col0 + r) * Kw + kw0 + ch;
            cpa16(sa, gp);
        }
        cpa_commit();
    };

    float acc[4][8][4];
#pragma unroll
    for (int mt = 0; mt < 4; mt++)
#pragma unroll
        for (int nt = 0; nt < 8; nt++)
#pragma unroll
            for (int e = 0; e < 4; e++) acc[mt][nt][e] = 0.f;

    const uint32_t bln = (lane & 7) + ((lane >> 4) << 3);
    const uint32_t blk = ((lane >> 3) & 1) << 3;
    const uint32_t arow = lane & 15;
    const uint32_t acol = (lane >> 4) << 3;

    prefetch(0);

    for (int kb = 0; kb < nkb; kb++) {
        cpa_wait<0>();
        __syncthreads();
        if (kb + 1 < nkb) prefetch(kb + 1);

        const uint32_t sb = smb + (kb & 1) * GSTB;
#pragma unroll
        for (int k16 = 0; k16 < 32; k16 += 16) {
            // B fragments: 8 n8-tiles = 4 pairs (hi) + 4 pairs (lo)
            uint32_t bh[4][4], bl[4][4];
#pragma unroll
            for (int pr = 0; pr < 4; pr++) {
                uint32_t off = (wn + pr * 16 + bln) * GPIT + (k16 + blk) * 2;
                ldmx4(bh[pr], sb + GBHB + off);
                ldmx4(bl[pr], sb + GBLB + off);
            }
#pragma unroll
            for (int mt = 0; mt < 4; mt++) {
                uint32_t ah[4], al[4];
                uint32_t off = (wm + mt * 16 + arow) * GPIT + (k16 + acol) * 2;
                ldmx4(ah, sb + GAHB + off);
                ldmx4(al, sb + GALB + off);
#pragma unroll
                for (int nt = 0; nt < 8; nt++) {
                    uint32_t b0h = bh[nt >> 1][(nt & 1) * 2];
                    uint32_t b1h = bh[nt >> 1][(nt & 1) * 2 + 1];
                    uint32_t b0l = bl[nt >> 1][(nt & 1) * 2];
                    uint32_t b1l = bl[nt >> 1][(nt & 1) * 2 + 1];
                    mma16816(acc[mt][nt], ah, b0h, b1h);
                    mma16816(acc[mt][nt], ah, b0l, b1l);
                    mma16816(acc[mt][nt], al, b0h, b1h);
                }
            }
        }
    }

#pragma unroll
    for (int mt = 0; mt < 4; mt++) {
#pragma unroll
        for (int nt = 0; nt < 8; nt++) {
            int row = row0 + wm + mt * 16 + (lane >> 2);
            int col = col0 + wn + nt * 8 + (lane & 3) * 2;
            float2 bz = *(const float2*)&bias[col];
            *(float2*)(C + (size_t)row * N + col) =
                make_float2(acc[mt][nt][0] + bz.x, acc[mt][nt][1] + bz.y);
            *(float2*)(C + (size_t)(row + 8) * N + col) =
                make_float2(acc[mt][nt][2] + bz.x, acc[mt][nt][3] + bz.y);
        }
    }
}

// ---------------------------------------------------------------------------
// RoPE table + apply/split/pack (unchanged)
// ---------------------------------------------------------------------------
__global__ void rope_table_kernel()
{
    int idx = blockIdx.x * 256 + threadIdx.x;
    int s  = idx >> 5;
    int dp = idx & 31;
    double inv = pow(10000.0, -((double)dp) / (double)HALF);
    double snd, csd;
    sincos((double)s * inv, &snd, &csd);
    g_ropet[idx * 2 + 0] = (float)csd;
    g_ropet[idx * 2 + 1] = (float)snd;
}

__global__ void rope_split_kernel()
{
    int idx = blockIdx.x * 256 + threadIdx.x;
    int j = idx & 31;
    int h = (idx >> 5) & 15;
    int s = (idx >> 9) & (SS - 1);
    int b = idx >> 20;
    const float* base = g_qkv + (size_t)(b * SS + s) * (3 * D_MODEL) + h * HDIM;
    int d0 = 2 * j, d1 = d0 + 1;
    int dp0 = d0 & 31, dp1 = d1 & 31;
    float cs0 = g_ropet[(s * 32 + dp0) * 2], sn0 = g_ropet[(s * 32 + dp0) * 2 + 1];
    float cs1 = g_ropet[(s * 32 + dp1) * 2], sn1 = g_ropet[(s * 32 + dp1) * 2 + 1];
    float qv0, qv1, kv0, kv1;
    if (d0 < 32) {
        qv0 = base[d0] * cs0 - base[d0 + 32] * sn0;
        qv1 = base[d1] * cs1 - base[d1 + 32] * sn1;
        kv0 = base[D_MODEL + d0] * cs0 - base[D_MODEL + d0 + 32] * sn0;
        kv1 = base[D_MODEL + d1] * cs1 - base[D_MODEL + d1 + 32] * sn1;
    } else {
        qv0 = base[dp0] * sn0 + base[d0] * cs0;
        qv1 = base[dp1] * sn1 + base[d1] * cs1;
        kv0 = base[D_MODEL + dp0] * sn0 + base[D_MODEL + d0] * cs0;
        kv1 = base[D_MODEL + dp1] * sn1 + base[D_MODEL + d1] * cs1;
    }
    qv0 *= 0.125f; qv1 *= 0.125f;
    float vv0 = base[2 * D_MODEL + d0], vv1 = base[2 * D_MODEL + d1];

    size_t o = ((size_t)(b * NHEADS + h) * SS + s) * 32 + j;
    float l0, l1;
    g_qh[o] = pack_hi(qv0, qv1, l0, l1); g_ql[o] = pack_bf(l0, l1);
    g_kh[o] = pack_hi(kv0, kv1, l0, l1); g_kl[o] = pack_bf(l0, l1);
    g_vh[o] = pack_hi(vv0, vv1, l0, l1); g_vl[o] = pack_bf(l0, l1);
}

// ===========================================================================
// Flash attention (unchanged from round 10): single-barrier pipeline + LJF.
// ===========================================================================
#define FQHB  0
#define FQLB  18432
#define FSB0  36864
#define FSTB  36864
#define FKHB  0
#define FKLB  9216
#define FVHB  18432
#define FVLB  27648
#define FSMEM 110592

__global__ void __launch_bounds__(256, 2)
flash_mma_kernel()
{
    extern __shared__ char fsm[];
    const uint32_t smb = smem_u32(fsm);
    uint32_t* smw = (uint32_t*)fsm;
    const int tid  = threadIdx.x;
    const int wid  = tid >> 5;
    const int lane = tid & 31;
    const int bh   = blockIdx.y;
    const int qb   = gridDim.x - 1 - blockIdx.x;    // heavy CTAs launch first
    const int q0   = qb * 128;
    const int wm   = wid * 16;
    const size_t rowbase = (size_t)bh * SS;

    const int ntiles = 2 * qb + 2;

    auto prefetch = [&](int kt) {
        const uint32_t sb = smb + FSB0 + (kt & 1) * FSTB;
        const int k0 = kt * 64;
#pragma unroll
        for (int i = 0; i < 8; i++) {
            int slot = tid + i * 256;
            int arr  = slot >> 9;
            int rem  = slot & 511;
            int r    = rem >> 3;
            int ch   = (rem & 7) << 2;
            uint32_t sa = sb + (uint32_t)arr * 9216 + r * 144 + ch * 4;
            size_t gi = (rowbase + k0 + r) * 32 + ch;
            const uint32_t* gp;
            if (arr == 0)      gp = g_kh + gi;
            else if (arr == 1) gp = g_kl + gi;
            else if (arr == 2) gp = g_vh + gi;
            else               gp = g_vl + gi;
            cpa16(sa, gp);
        }
        cpa_commit();
    };

    prefetch(0);

    // ---- Q fill (plain uint4 copies) ----
#pragma unroll
    for (int i = 0; i < 4; i++) {
        int slot = tid + i * 256;
        int r = slot >> 3, c = (slot & 7) * 4;
        size_t gi = (rowbase + q0 + r) * 32 + c;
        *(uint4*)&smw[(FQHB >> 2) + r * 36 + c] = *(const uint4*)&g_qh[gi];
        *(uint4*)&smw[(FQLB >> 2) + r * 36 + c] = *(const uint4*)&g_ql[gi];
    }
    __syncthreads();

    // ---- hoist Q a-frags ----
    uint32_t qh[4][4], ql[4][4];
    {
        const uint32_t arow = lane & 15;
        const uint32_t acol = (lane >> 4) << 3;
#pragma unroll
        for (int ks = 0; ks < 4; ks++) {
            uint32_t off = (wm + arow) * 144 + (ks * 16 + acol) * 2;
            ldmx4(qh[ks], smb + FQHB + off);
            ldmx4(ql[ks], smb + FQLB + off);
        }
    }

    float o[8][4];
#pragma unroll
    for (int nt = 0; nt < 8; nt++)
#pragma unroll
        for (int e = 0; e < 4; e++) o[nt][e] = 0.f;
    float mrun[2] = {-INFINITY, -INFINITY};
    float lrun[2] = {0.f, 0.f};

    const uint32_t bln = (lane & 7) + ((lane >> 4) << 3);
    const uint32_t blk = ((lane >> 3) & 1) << 3;
    const uint32_t vrow = (lane & 7) + (((lane >> 3) & 1) << 3);
    const uint32_t vcol = (lane >> 4) << 3;

    for (int kt = 0; kt < ntiles; kt++) {
        const int k0 = kt * 64;
        cpa_wait<0>();
        __syncthreads();
        if (kt + 1 < ntiles) prefetch(kt + 1);

        const uint32_t sb = smb + FSB0 + (kt & 1) * FSTB;

        if (k0 <= q0 + wm + 15) {
            // ---- S = Q K^T ----
            float sc[8][4];
#pragma unroll
            for (int nt = 0; nt < 8; nt++)
#pragma unroll
                for (int e = 0; e < 4; e++) sc[nt][e] = 0.f;
#pragma unroll
            for (int ks = 0; ks < 4; ks++) {
#pragma unroll
                for (int pr = 0; pr < 4; pr++) {
                    uint32_t kh[4], kl[4];
                    uint32_t off = (pr * 16 + bln) * 144 + (ks * 16 + blk) * 2;
                    ldmx4(kh, sb + FKHB + off);
                    ldmx4(kl, sb + FKLB + off);
                    mma16816(sc[2*pr],   qh[ks], kh[0], kh[1]);
                    mma16816(sc[2*pr],   qh[ks], kl[0], kl[1]);
                    mma16816(sc[2*pr],   ql[ks], kh[0], kh[1]);
                    mma16816(sc[2*pr+1], qh[ks], kh[2], kh[3]);
                    mma16816(sc[2*pr+1], qh[ks], kl[2], kl[3]);
                    mma16816(sc[2*pr+1], ql[ks], kh[2], kh[3]);
                }
            }

            // ---- causal mask on straddling tiles ----
            if (k0 + 63 > q0 + wm) {
                int row0g = q0 + wm + (lane >> 2);
#pragma unroll
                for (int nt = 0; nt < 8; nt++) {
                    int colg = k0 + nt * 8 + (lane & 3) * 2;
                    if (colg     > row0g)     sc[nt][0] = -INFINITY;
                    if (colg + 1 > row0g)     sc[nt][1] = -INFINITY;
                    if (colg     > row0g + 8) sc[nt][2] = -INFINITY;
                    if (colg + 1 > row0g + 8) sc[nt][3] = -INFINITY;
                }
            }

            // ---- online softmax ----
#pragma unroll
            for (int hrow = 0; hrow < 2; hrow++) {
                const int e0 = hrow * 2;
                float mx = -INFINITY;
#pragma unroll
                for (int nt = 0; nt < 8; nt++)
                    mx = fmaxf(mx, fmaxf(sc[nt][e0], sc[nt][e0 + 1]));
                mx = fmaxf(mx, __shfl_xor_sync(0xffffffffu, mx, 1));
                mx = fmaxf(mx, __shfl_xor_sync(0xffffffffu, mx, 2));
                float mn    = fmaxf(mrun[hrow], mx);
                float alpha = __expf(mrun[hrow] - mn);
                float ls = 0.f;
#pragma unroll
                for (int nt = 0; nt < 8; nt++) {
                    float p0 = __expf(sc[nt][e0]     - mn);
                    float p1 = __expf(sc[nt][e0 + 1] - mn);
                    sc[nt][e0] = p0; sc[nt][e0 + 1] = p1;
                    ls += p0 + p1;
                }
                ls += __shfl_xor_sync(0xffffffffu, ls, 1);
                ls += __shfl_xor_sync(0xffffffffu, ls, 2);
                lrun[hrow] = lrun[hrow] * alpha + ls;
                mrun[hrow] = mn;
#pragma unroll
                for (int nt = 0; nt < 8; nt++) {
                    o[nt][e0] *= alpha; o[nt][e0 + 1] *= alpha;
                }
            }

            // ---- O += P V ----
#pragma unroll
            for (int ks = 0; ks < 4; ks++) {
                uint32_t pa[4], pl[4];
                {
                    float l0, l1, l2, l3;
                    pa[0] = pack_hi(sc[2*ks][0],   sc[2*ks][1],   l0, l1);
                    pa[1] = pack_hi(sc[2*ks][2],   sc[2*ks][3],   l2, l3);
                    pl[0] = pack_bf(l0, l1);
                    pl[1] = pack_bf(l2, l3);
                    pa[2] = pack_hi(sc[2*ks+1][0], sc[2*ks+1][1], l0, l1);
                    pa[3] = pack_hi(sc[2*ks+1][2], sc[2*ks+1][3], l2, l3);
                    pl[2] = pack_bf(l0, l1);
                    pl[3] = pack_bf(l2, l3);
                }
#pragma unroll
                for (int dp = 0; dp < 4; dp++) {
                    uint32_t vh[4], vl[4];
                    uint32_t off = (ks * 16 + vrow) * 144 + (dp * 16 + vcol) * 2;
                    ldmx4t(vh, sb + FVHB + off);
                    ldmx4t(vl, sb + FVLB + off);
                    mma16816(o[2*dp],   pa, vh[0], vh[1]);
                    mma16816(o[2*dp],   pa, vl[0], vl[1]);
                    mma16816(o[2*dp],   pl, vh[0], vh[1]);
                    mma16816(o[2*dp+1], pa, vh[2], vh[3]);
                    mma16816(o[2*dp+1], pa, vl[2], vl[3]);
                    mma16816(o[2*dp+1], pl, vh[2], vh[3]);
                }
            }
        }
    }

    // ---- epilogue: normalize + pack hi/lo directly ----
    const int b = bh >> 4, h = bh & 15;
    const float inv0 = 1.f / lrun[0];
    const float inv1 = 1.f / lrun[1];
    int row0g = q0 + wm + (lane >> 2);
#pragma unroll
    for (int nt = 0; nt < 8; nt++) {
        int cw = h * 32 + nt * 4 + (lane & 3);
        size_t o0 = (size_t)(b * SS + row0g) * KW + cw;
        size_t o1 = (size_t)(b * SS + row0g + 8) * KW + cw;
        float l0, l1;
        g_ah[o0] = pack_hi(o[nt][0] * inv0, o[nt][1] * inv0, l0, l1);
        g_al[o0] = pack_bf(l0, l1);
        g_ah[o1] = pack_hi(o[nt][2] * inv1, o[nt][3] * inv1, l0, l1);
        g_al[o1] = pack_bf(l0, l1);
    }
}

// ---------------------------------------------------------------------------
extern "C" void kernel_launch(void* const* d_in, const int* in_sizes, int n_in,
                              void* d_out, int out_size)
{
    const float* x     = 0;
    const float* qkv_w = 0;
    const float* qkv_b = 0;
    const float* out_w = 0;
    const float* out_b = 0;
    for (int i = 0; i < n_in; i++) {
        switch (in_sizes[i]) {
            case MTOK * D_MODEL:            x     = (const float*)d_in[i]; break;
            case 3 * D_MODEL * D_MODEL:     qkv_w = (const float*)d_in[i]; break;
            case 3 * D_MODEL:               qkv_b = (const float*)d_in[i]; break;
            case D_MODEL * D_MODEL:         out_w = (const float*)d_in[i]; break;
            case D_MODEL:                   out_b = (const float*)d_in[i]; break;
            default: break;
        }
    }
    float* out = (float*)d_out;

    float* qkv_p;
    uint32_t *xh_p, *xl_p, *w1h_p, *w1l_p, *w2h_p, *w2l_p, *ah_p, *al_p;
    cudaGetSymbolAddress((void**)&qkv_p, g_qkv);
    cudaGetSymbolAddress((void**)&xh_p,  g_xh);  cudaGetSymbolAddress((void**)&xl_p,  g_xl);
    cudaGetSymbolAddress((void**)&w1h_p, g_w1h); cudaGetSymbolAddress((void**)&w1l_p, g_w1l);
    cudaGetSymbolAddress((void**)&w2h_p, g_w2h); cudaGetSymbolAddress((void**)&w2l_p, g_w2l);
    cudaGetSymbolAddress((void**)&ah_p,  g_ah);  cudaGetSymbolAddress((void**)&al_p,  g_al);

    cudaFuncSetAttribute(gemm_pk,
                         cudaFuncAttributeMaxDynamicSharedMemorySize, GSMEM);
    cudaFuncSetAttribute(flash_mma_kernel,
                         cudaFuncAttributeMaxDynamicSharedMemorySize, FSMEM);

    // 0) pre-split inputs to packed bf16 hi/lo
    split_pack<<<MTOK * KW / 256, 256>>>((const float2*)x, xh_p, xl_p, MTOK * KW);
    split_pack<<<3 * D_MODEL * KW / 256, 256>>>((const float2*)qkv_w, w1h_p, w1l_p,
                                                3 * D_MODEL * KW);
    split_pack<<<D_MODEL * KW / 256, 256>>>((const float2*)out_w, w2h_p, w2l_p,
                                            D_MODEL * KW);

    // 1) QKV projection (128-thread CTAs, 64x64 warp tiles)
    gemm_pk<<<dim3((3 * D_MODEL) / 128, MTOK / 128), 128, GSMEM>>>(
        xh_p, xl_p, w1h_p, w1l_p, qkv_b, qkv_p, MTOK, 3 * D_MODEL, KW);

    // 2) RoPE table + apply/split/pack
    rope_table_kernel<<<SS * HALF / 256, 256>>>();
    rope_split_kernel<<<MTOK * NHEADS * 32 / 256, 256>>>();

    // 3) causal flash attention
    flash_mma_kernel<<<dim3(SS / 128, BB * NHEADS), 256, FSMEM>>>();

    // 4) output projection
    gemm_pk<<<dim3(D_MODEL / 128, MTOK / 128), 128, GSMEM>>>(
        ah_p, al_p, w2h_p, w2l_p, out_b, out, MTOK, D_MODEL, KW);
}

// round 14
// speedup vs baseline: 1.0427x; 1.0367x over previous
#include <cuda_runtime.h>
#include <cuda_bf16.h>
#include <cuda_fp16.h>
#include <math.h>
#include <stdint.h>

#define D_MODEL 1024
#define NHEADS  16
#define HDIM    64
#define HALF    32
#define BB      2
#define SS      2048
#define MTOK    (BB*SS)          // 4096 tokens
#define NROWS   (BB*NHEADS*SS)   // 65536 head-rows
#define KW      (D_MODEL/2)      // 512 packed words per row

// Scratch (static __device__ arrays — no allocations allowed)
__device__ float g_qkv[MTOK * 3 * D_MODEL];     // GEMM1 output (fp32)
__device__ float g_ropet[SS * HALF * 2];        // cos/sin table
// packed bf16 hi/lo pairs (2 bf16 per uint32)
__device__ __align__(16) uint32_t g_xh [MTOK * KW],      g_xl [MTOK * KW];
__device__ __align__(16) uint32_t g_w1h[3*D_MODEL * KW], g_w1l[3*D_MODEL * KW];
__device__ __align__(16) uint32_t g_w2h[D_MODEL * KW],   g_w2l[D_MODEL * KW];
__device__ __align__(16) uint32_t g_ah [MTOK * KW],      g_al [MTOK * KW];   // flash out
__device__ __align__(16) uint32_t g_qh[NROWS*32], g_ql[NROWS*32];
__device__ __align__(16) uint32_t g_kh[NROWS*32], g_kl[NROWS*32];
__device__ __align__(16) uint32_t g_vh[NROWS*32], g_vl[NROWS*32];

// ===========================================================================
// helpers
// ===========================================================================
__device__ __forceinline__ uint32_t smem_u32(const void* p) {
    uint32_t a;
    asm("{ .reg .u64 t; cvta.to.shared.u64 t, %1; cvt.u32.u64 %0, t; }"
        : "=r"(a) : "l"(p));
    return a;
}
__device__ __forceinline__ void ldmx4(uint32_t* r, uint32_t addr) {
    asm volatile("ldmatrix.sync.aligned.m8n8.x4.shared.b16 {%0,%1,%2,%3}, [%4];"
                 : "=r"(r[0]), "=r"(r[1]), "=r"(r[2]), "=r"(r[3]) : "r"(addr));
}
__device__ __forceinline__ void ldmx4t(uint32_t* r, uint32_t addr) {
    asm volatile("ldmatrix.sync.aligned.m8n8.x4.trans.shared.b16 {%0,%1,%2,%3}, [%4];"
                 : "=r"(r[0]), "=r"(r[1]), "=r"(r[2]), "=r"(r[3]) : "r"(addr));
}
__device__ __forceinline__ void mma16816(float* c, const uint32_t* a,
                                         uint32_t b0, uint32_t b1) {
    asm volatile(
        "mma.sync.aligned.m16n8k16.row.col.f32.bf16.bf16.f32 "
        "{%0,%1,%2,%3}, {%4,%5,%6,%7}, {%8,%9}, {%0,%1,%2,%3};"
        : "+f"(c[0]), "+f"(c[1]), "+f"(c[2]), "+f"(c[3])
        : "r"(a[0]), "r"(a[1]), "r"(a[2]), "r"(a[3]), "r"(b0), "r"(b1));
}
__device__ __forceinline__ uint32_t pack_hi(float x, float y,
                                            float& rx, float& ry) {
    __nv_bfloat16 hx = __float2bfloat16(x);
    __nv_bfloat16 hy = __float2bfloat16(y);
    rx = x - __bfloat162float(hx);
    ry = y - __bfloat162float(hy);
    return ((uint32_t)__bfloat16_as_ushort(hy) << 16) |
           (uint32_t)__bfloat16_as_ushort(hx);
}
__device__ __forceinline__ uint32_t pack_bf(float x, float y) {
    return ((uint32_t)__bfloat16_as_ushort(__float2bfloat16(y)) << 16) |
           (uint32_t)__bfloat16_as_ushort(__float2bfloat16(x));
}
__device__ __forceinline__ void cpa16(uint32_t saddr, const void* g) {
    asm volatile("cp.async.cg.shared.global [%0], [%1], 16;"
                 :: "r"(saddr), "l"(g));
}
__device__ __forceinline__ void cpa_commit() {
    asm volatile("cp.async.commit_group;" ::: "memory");
}
template <int N> __device__ __forceinline__ void cpa_wait() {
    asm volatile("cp.async.wait_group %0;" :: "n"(N) : "memory");
}

// ===========================================================================
// split_pack_all: ONE launch converting x, qkv_w, out_w to packed bf16 hi/lo
// ===========================================================================
#define NX  (MTOK * KW)            // 2097152
#define NW1 (3 * D_MODEL * KW)     // 1572864
#define NW2 (D_MODEL * KW)         // 524288

__global__ void split_pack_all(const float2* __restrict__ x,
                               const float2* __restrict__ w1,
                               const float2* __restrict__ w2)
{
    int i = blockIdx.x * 256 + threadIdx.x;
    const float2* in;
    uint32_t *hi, *lo;
    int j;
    if (i < NX)            { in = x;  hi = g_xh;  lo = g_xl;  j = i; }
    else if (i < NX + NW1) { in = w1; hi = g_w1h; lo = g_w1l; j = i - NX; }
    else                   { in = w2; hi = g_w2h; lo = g_w2l; j = i - NX - NW1; }
    float2 v = in[j];
    float l0, l1;
    hi[j] = pack_hi(v.x, v.y, l0, l1);
    lo[j] = pack_bf(l0, l1);
}

// ===========================================================================
// GEMM (reverted to R9 best-measured config): 256 thr, 8 warps 2x4,
// warp tile 64x32, BK=32, 2 stages x 40KB, single barrier per k-block.
// ===========================================================================
#define GSTB  40960
#define GAHB  0
#define GALB  10240
#define GBHB  20480
#define GBLB  30720
#define GSMEM (2*GSTB)       // 81920

__global__ void __launch_bounds__(256, 2)
gemm_pk(const uint32_t* __restrict__ Apk_h, const uint32_t* __restrict__ Apk_l,
        const uint32_t* __restrict__ Wpk_h, const uint32_t* __restrict__ Wpk_l,
        const float* __restrict__ bias, float* __restrict__ C,
        int M, int N, int Kw)
{
    extern __shared__ char sm[];
    const uint32_t smb = smem_u32(sm);
    const int tid  = threadIdx.x;
    const int wid  = tid >> 5;
    const int lane = tid & 31;
    const int row0 = blockIdx.y * 128;
    const int col0 = blockIdx.x * 128;
    const int wm   = (wid >> 2) * 64;
    const int wn   = (wid & 3) * 32;

    const int nkb = Kw >> 4;

    auto prefetch = [&](int kb) {
        const uint32_t sb = smb + (kb & 1) * GSTB;
        const int kw0 = kb << 4;
#pragma unroll
        for (int i = 0; i < 8; i++) {
            int slot = tid + i * 256;
            int arr  = slot >> 9;
            int rem  = slot & 511;
            int r    = rem >> 2;
            int ch   = (rem & 3) << 2;
            uint32_t sa = sb + (uint32_t)arr * 10240 + r * 80 + ch * 4;
            const uint32_t* gp;
            if (arr == 0)      gp = Apk_h + (size_t)(row0 + r) * Kw + kw0 + ch;
            else if (arr == 1) gp = Apk_l + (size_t)(row0 + r) * Kw + kw0 + ch;
            else if (arr == 2) gp = Wpk_h + (size_t)(col0 + r) * Kw + kw0 + ch;
            else               gp = Wpk_l + (size_t)(col0 + r) * Kw + kw0 + ch;
            cpa16(sa, gp);
        }
        cpa_commit();
    };

    float acc[4][4][4];
#pragma unroll
    for (int mt = 0; mt < 4; mt++)
#pragma unroll
        for (int nt = 0; nt < 4; nt++)
#pragma unroll
            for (int e = 0; e < 4; e++) acc[mt][nt][e] = 0.f;

    const uint32_t bln = (lane & 7) + ((lane >> 4) << 3);
    const uint32_t blk = ((lane >> 3) & 1) << 3;
    const uint32_t arow = lane & 15;
    const uint32_t acol = (lane >> 4) << 3;

    prefetch(0);

    for (int kb = 0; kb < nkb; kb++) {
        cpa_wait<0>();
        __syncthreads();
        if (kb + 1 < nkb) prefetch(kb + 1);

        const uint32_t sb = smb + (kb & 1) * GSTB;
#pragma unroll
        for (int k16 = 0; k16 < 32; k16 += 16) {
            uint32_t bh[2][4], bl[2][4];
#pragma unroll
            for (int pr = 0; pr < 2; pr++) {
                uint32_t off = (wn + pr * 16 + bln) * 80 + (k16 + blk) * 2;
                ldmx4(bh[pr], sb + GBHB + off);
                ldmx4(bl[pr], sb + GBLB + off);
            }
#pragma unroll
            for (int mt = 0; mt < 4; mt++) {
                uint32_t ah[4], al[4];
                uint32_t off = (wm + mt * 16 + arow) * 80 + (k16 + acol) * 2;
                ldmx4(ah, sb + GAHB + off);
                ldmx4(al, sb + GALB + off);
#pragma unroll
                for (int nt = 0; nt < 4; nt++) {
                    uint32_t b0h = bh[nt >> 1][(nt & 1) * 2];
                    uint32_t b1h = bh[nt >> 1][(nt & 1) * 2 + 1];
                    uint32_t b0l = bl[nt >> 1][(nt & 1) * 2];
                    uint32_t b1l = bl[nt >> 1][(nt & 1) * 2 + 1];
                    mma16816(acc[mt][nt], ah, b0h, b1h);
                    mma16816(acc[mt][nt], ah, b0l, b1l);
                    mma16816(acc[mt][nt], al, b0h, b1h);
                }
            }
        }
    }

#pragma unroll
    for (int mt = 0; mt < 4; mt++) {
#pragma unroll
        for (int nt = 0; nt < 4; nt++) {
            int row = row0 + wm + mt * 16 + (lane >> 2);
            int col = col0 + wn + nt * 8 + (lane & 3) * 2;
            float2 bz = *(const float2*)&bias[col];
            *(float2*)(C + (size_t)row * N + col) =
                make_float2(acc[mt][nt][0] + bz.x, acc[mt][nt][1] + bz.y);
            *(float2*)(C + (size_t)(row + 8) * N + col) =
                make_float2(acc[mt][nt][2] + bz.x, acc[mt][nt][3] + bz.y);
        }
    }
}

// ---------------------------------------------------------------------------
// RoPE table + apply/split/pack.
// Q is scaled by 0.125 * log2(e): flash softmax runs in log2 domain.
// ---------------------------------------------------------------------------
#define QSCALE 0.1803368801111244f   // 0.125 * 1.4426950408889634

__global__ void rope_table_kernel()
{
    int idx = blockIdx.x * 256 + threadIdx.x;
    int s  = idx >> 5;
    int dp = idx & 31;
    double inv = pow(10000.0, -((double)dp) / (double)HALF);
    double snd, csd;
    sincos((double)s * inv, &snd, &csd);
    g_ropet[idx * 2 + 0] = (float)csd;
    g_ropet[idx * 2 + 1] = (float)snd;
}

__global__ void rope_split_kernel()
{
    int idx = blockIdx.x * 256 + threadIdx.x;
    int j = idx & 31;
    int h = (idx >> 5) & 15;
    int s = (idx >> 9) & (SS - 1);
    int b = idx >> 20;
    const float* base = g_qkv + (size_t)(b * SS + s) * (3 * D_MODEL) + h * HDIM;
    int d0 = 2 * j, d1 = d0 + 1;
    int dp0 = d0 & 31, dp1 = d1 & 31;
    float cs0 = g_ropet[(s * 32 + dp0) * 2], sn0 = g_ropet[(s * 32 + dp0) * 2 + 1];
    float cs1 = g_ropet[(s * 32 + dp1) * 2], sn1 = g_ropet[(s * 32 + dp1) * 2 + 1];
    float qv0, qv1, kv0, kv1;
    if (d0 < 32) {
        qv0 = base[d0] * cs0 - base[d0 + 32] * sn0;
        qv1 = base[d1] * cs1 - base[d1 + 32] * sn1;
        kv0 = base[D_MODEL + d0] * cs0 - base[D_MODEL + d0 + 32] * sn0;
        kv1 = base[D_MODEL + d1] * cs1 - base[D_MODEL + d1 + 32] * sn1;
    } else {
        qv0 = base[dp0] * sn0 + base[d0] * cs0;
        qv1 = base[dp1] * sn1 + base[d1] * cs1;
        kv0 = base[D_MODEL + dp0] * sn0 + base[D_MODEL + d0] * cs0;
        kv1 = base[D_MODEL + dp1] * sn1 + base[D_MODEL + d1] * cs1;
    }
    qv0 *= QSCALE; qv1 *= QSCALE;   // fold 1/sqrt(64) AND log2(e)
    float vv0 = base[2 * D_MODEL + d0], vv1 = base[2 * D_MODEL + d1];

    size_t o = ((size_t)(b * NHEADS + h) * SS + s) * 32 + j;
    float l0, l1;
    g_qh[o] = pack_hi(qv0, qv1, l0, l1); g_ql[o] = pack_bf(l0, l1);
    g_kh[o] = pack_hi(kv0, kv1, l0, l1); g_kl[o] = pack_bf(l0, l1);
    g_vh[o] = pack_hi(vv0, vv1, l0, l1); g_vl[o] = pack_bf(l0, l1);
}

// ===========================================================================
// Flash attention v7: log2-domain softmax with h2exp2 (f16x2 MUFU halving).
// Single-barrier cp.async pipeline + LJF scheduling (unchanged).
// ===========================================================================
#define FQHB  0
#define FQLB  18432
#define FSB0  36864
#define FSTB  36864
#define FKHB  0
#define FKLB  9216
#define FVHB  18432
#define FVLB  27648
#define FSMEM 110592

__global__ void __launch_bounds__(256, 2)
flash_mma_kernel()
{
    extern __shared__ char fsm[];
    const uint32_t smb = smem_u32(fsm);
    uint32_t* smw = (uint32_t*)fsm;
    const int tid  = threadIdx.x;
    const int wid  = tid >> 5;
    const int lane = tid & 31;
    const int bh   = blockIdx.y;
    const int qb   = gridDim.x - 1 - blockIdx.x;    // heavy CTAs launch first
    const int q0   = qb * 128;
    const int wm   = wid * 16;
    const size_t rowbase = (size_t)bh * SS;

    const int ntiles = 2 * qb + 2;

    auto prefetch = [&](int kt) {
        const uint32_t sb = smb + FSB0 + (kt & 1) * FSTB;
        const int k0 = kt * 64;
#pragma unroll
        for (int i = 0; i < 8; i++) {
            int slot = tid + i * 256;
            int arr  = slot >> 9;
            int rem  = slot & 511;
            int r    = rem >> 3;
            int ch   = (rem & 7) << 2;
            uint32_t sa = sb + (uint32_t)arr * 9216 + r * 144 + ch * 4;
            size_t gi = (rowbase + k0 + r) * 32 + ch;
            const uint32_t* gp;
            if (arr == 0)      gp = g_kh + gi;
            else if (arr == 1) gp = g_kl + gi;
            else if (arr == 2) gp = g_vh + gi;
            else               gp = g_vl + gi;
            cpa16(sa, gp);
        }
        cpa_commit();
    };

    prefetch(0);

    // ---- Q fill (plain uint4 copies) ----
#pragma unroll
    for (int i = 0; i < 4; i++) {
        int slot = tid + i * 256;
        int r = slot >> 3, c = (slot & 7) * 4;
        size_t gi = (rowbase + q0 + r) * 32 + c;
        *(uint4*)&smw[(FQHB >> 2) + r * 36 + c] = *(const uint4*)&g_qh[gi];
        *(uint4*)&smw[(FQLB >> 2) + r * 36 + c] = *(const uint4*)&g_ql[gi];
    }
    __syncthreads();

    // ---- hoist Q a-frags ----
    uint32_t qh[4][4], ql[4][4];
    {
        const uint32_t arow = lane & 15;
        const uint32_t acol = (lane >> 4) << 3;
#pragma unroll
        for (int ks = 0; ks < 4; ks++) {
            uint32_t off = (wm + arow) * 144 + (ks * 16 + acol) * 2;
            ldmx4(qh[ks], smb + FQHB + off);
            ldmx4(ql[ks], smb + FQLB + off);
        }
    }

    float o[8][4];
#pragma unroll
    for (int nt = 0; nt < 8; nt++)
#pragma unroll
        for (int e = 0; e < 4; e++) o[nt][e] = 0.f;
    float mrun[2] = {-INFINITY, -INFINITY};
    float lrun[2] = {0.f, 0.f};

    const uint32_t bln = (lane & 7) + ((lane >> 4) << 3);
    const uint32_t blk = ((lane >> 3) & 1) << 3;
    const uint32_t vrow = (lane & 7) + (((lane >> 3) & 1) << 3);
    const uint32_t vcol = (lane >> 4) << 3;

    for (int kt = 0; kt < ntiles; kt++) {
        const int k0 = kt * 64;
        cpa_wait<0>();
        __syncthreads();
        if (kt + 1 < ntiles) prefetch(kt + 1);

        const uint32_t sb = smb + FSB0 + (kt & 1) * FSTB;

        if (k0 <= q0 + wm + 15) {
            // ---- S = Q K^T  (logits already in log2 units via QSCALE) ----
            float sc[8][4];
#pragma unroll
            for (int nt = 0; nt < 8; nt++)
#pragma unroll
                for (int e = 0; e < 4; e++) sc[nt][e] = 0.f;
#pragma unroll
            for (int ks = 0; ks < 4; ks++) {
#pragma unroll
                for (int pr = 0; pr < 4; pr++) {
                    uint32_t kh[4], kl[4];
                    uint32_t off = (pr * 16 + bln) * 144 + (ks * 16 + blk) * 2;
                    ldmx4(kh, sb + FKHB + off);
                    ldmx4(kl, sb + FKLB + off);
                    mma16816(sc[2*pr],   qh[ks], kh[0], kh[1]);
                    mma16816(sc[2*pr],   qh[ks], kl[0], kl[1]);
                    mma16816(sc[2*pr],   ql[ks], kh[0], kh[1]);
                    mma16816(sc[2*pr+1], qh[ks], kh[2], kh[3]);
                    mma16816(sc[2*pr+1], qh[ks], kl[2], kl[3]);
                    mma16816(sc[2*pr+1], ql[ks], kh[2], kh[3]);
                }
            }

            // ---- causal mask on straddling tiles ----
            if (k0 + 63 > q0 + wm) {
                int row0g = q0 + wm + (lane >> 2);
#pragma unroll
                for (int nt = 0; nt < 8; nt++) {
                    int colg = k0 + nt * 8 + (lane & 3) * 2;
                    if (colg     > row0g)     sc[nt][0] = -INFINITY;
                    if (colg + 1 > row0g)     sc[nt][1] = -INFINITY;
                    if (colg     > row0g + 8) sc[nt][2] = -INFINITY;
                    if (colg + 1 > row0g + 8) sc[nt][3] = -INFINITY;
                }
            }

            // ---- online softmax (log2 domain, f16x2 exp2) ----
#pragma unroll
            for (int hrow = 0; hrow < 2; hrow++) {
                const int e0 = hrow * 2;
                float mx = -INFINITY;
#pragma unroll
                for (int nt = 0; nt < 8; nt++)
                    mx = fmaxf(mx, fmaxf(sc[nt][e0], sc[nt][e0 + 1]));
                mx = fmaxf(mx, __shfl_xor_sync(0xffffffffu, mx, 1));
                mx = fmaxf(mx, __shfl_xor_sync(0xffffffffu, mx, 2));
                float mn    = fmaxf(mrun[hrow], mx);
                float alpha = exp2f(mrun[hrow] - mn);
                float ls = 0.f;
#pragma unroll
                for (int nt = 0; nt < 8; nt++) {
                    half2 hp = h2exp2(__float22half2_rn(
                        make_float2(sc[nt][e0] - mn, sc[nt][e0 + 1] - mn)));
                    float2 pf = __half22float2(hp);
                    sc[nt][e0] = pf.x; sc[nt][e0 + 1] = pf.y;
                    ls += pf.x + pf.y;
                }
                ls += __shfl_xor_sync(0xffffffffu, ls, 1);
                ls += __shfl_xor_sync(0xffffffffu, ls, 2);
                lrun[hrow] = lrun[hrow] * alpha + ls;
                mrun[hrow] = mn;
#pragma unroll
                for (int nt = 0; nt < 8; nt++) {
                    o[nt][e0] *= alpha; o[nt][e0 + 1] *= alpha;
                }
            }

            // ---- O += P V (3-term split; P lo is exact residual of f16 p) ----
#pragma unroll
            for (int ks = 0; ks < 4; ks++) {
                uint32_t pa[4], pl[4];
                {
                    float l0, l1, l2, l3;
                    pa[0] = pack_hi(sc[2*ks][0],   sc[2*ks][1],   l0, l1);
                    pa[1] = pack_hi(sc[2*ks][2],   sc[2*ks][3],   l2, l3);
                    pl[0] = pack_bf(l0, l1);
                    pl[1] = pack_bf(l2, l3);
                    pa[2] = pack_hi(sc[2*ks+1][0], sc[2*ks+1][1], l0, l1);
                    pa[3] = pack_hi(sc[2*ks+1][2], sc[2*ks+1][3], l2, l3);
                    pl[2] = pack_bf(l0, l1);
                    pl[3] = pack_bf(l2, l3);
                }
#pragma unroll
                for (int dp = 0; dp < 4; dp++) {
                    uint32_t vh[4], vl[4];
                    uint32_t off = (ks * 16 + vrow) * 144 + (dp * 16 + vcol) * 2;
                    ldmx4t(vh, sb + FVHB + off);
                    ldmx4t(vl, sb + FVLB + off);
                    mma16816(o[2*dp],   pa, vh[0], vh[1]);
                    mma16816(o[2*dp],   pa, vl[0], vl[1]);
                    mma16816(o[2*dp],   pl, vh[0], vh[1]);
                    mma16816(o[2*dp+1], pa, vh[2], vh[3]);
                    mma16816(o[2*dp+1], pa, vl[2], vl[3]);
                    mma16816(o[2*dp+1], pl, vh[2], vh[3]);
                }
            }
        }
        __syncthreads();
    }

    // ---- epilogue: normalize + pack hi/lo directly ----
    const int b = bh >> 4, h = bh & 15;
    const float inv0 = 1.f / lrun[0];
    const float inv1 = 1.f / lrun[1];
    int row0g = q0 + wm + (lane >> 2);
#pragma unroll
    for (int nt = 0; nt < 8; nt++) {
        int cw = h * 32 + nt * 4 + (lane & 3);
        size_t o0 = (size_t)(b * SS + row0g) * KW + cw;
        size_t o1 = (size_t)(b * SS + row0g + 8) * KW + cw;
        float l0, l1;
        g_ah[o0] = pack_hi(o[nt][0] * inv0, o[nt][1] * inv0, l0, l1);
        g_al[o0] = pack_bf(l0, l1);
        g_ah[o1] = pack_hi(o[nt][2] * inv1, o[nt][3] * inv1, l0, l1);
        g_al[o1] = pack_bf(l0, l1);
    }
}

// ---------------------------------------------------------------------------
extern "C" void kernel_launch(void* const* d_in, const int* in_sizes, int n_in,
                              void* d_out, int out_size)
{
    const float* x     = 0;
    const float* qkv_w = 0;
    const float* qkv_b = 0;
    const float* out_w = 0;
    const float* out_b = 0;
    for (int i = 0; i < n_in; i++) {
        switch (in_sizes[i]) {
            case MTOK * D_MODEL:            x     = (const float*)d_in[i]; break;
            case 3 * D_MODEL * D_MODEL:     qkv_w = (const float*)d_in[i]; break;
            case 3 * D_MODEL:               qkv_b = (const float*)d_in[i]; break;
            case D_MODEL * D_MODEL:         out_w = (const float*)d_in[i]; break;
            case D_MODEL:                   out_b = (const float*)d_in[i]; break;
            default: break;
        }
    }
    float* out = (float*)d_out;

    float* qkv_p;
    uint32_t *xh_p, *xl_p, *w1h_p, *w1l_p, *w2h_p, *w2l_p, *ah_p, *al_p;
    cudaGetSymbolAddress((void**)&qkv_p, g_qkv);
    cudaGetSymbolAddress((void**)&xh_p,  g_xh);  cudaGetSymbolAddress((void**)&xl_p,  g_xl);
    cudaGetSymbolAddress((void**)&w1h_p, g_w1h); cudaGetSymbolAddress((void**)&w1l_p, g_w1l);
    cudaGetSymbolAddress((void**)&w2h_p, g_w2h); cudaGetSymbolAddress((void**)&w2l_p, g_w2l);
    cudaGetSymbolAddress((void**)&ah_p,  g_ah);  cudaGetSymbolAddress((void**)&al_p,  g_al);

    cudaFuncSetAttribute(gemm_pk,
                         cudaFuncAttributeMaxDynamicSharedMemorySize, GSMEM);
    cudaFuncSetAttribute(flash_mma_kernel,
                         cudaFuncAttributeMaxDynamicSharedMemorySize, FSMEM);

    // 0) pre-split inputs to packed bf16 hi/lo (single fused launch)
    split_pack_all<<<(NX + NW1 + NW2) / 256, 256>>>(
        (const float2*)x, (const float2*)qkv_w, (const float2*)out_w);

    // 1) QKV projection
    gemm_pk<<<dim3((3 * D_MODEL) / 128, MTOK / 128), 256, GSMEM>>>(
        xh_p, xl_p, w1h_p, w1l_p, qkv_b, qkv_p, MTOK, 3 * D_MODEL, KW);

    // 2) RoPE table + apply/split/pack (Q scaled by 0.125*log2e)
    rope_table_kernel<<<SS * HALF / 256, 256>>>();
    rope_split_kernel<<<MTOK * NHEADS * 32 / 256, 256>>>();

    // 3) causal flash attention (log2-domain softmax)
    flash_mma_kernel<<<dim3(SS / 128, BB * NHEADS), 256, FSMEM>>>();

    // 4) output projection
    gemm_pk<<<dim3(D_MODEL / 128, MTOK / 128), 256, GSMEM>>>(
        ah_p, al_p, w2h_p, w2l_p, out_b, out, MTOK, D_MODEL, KW);
}